// round 2
// baseline (speedup 1.0000x reference)
#include <cuda_runtime.h>

// Problem constants (fixed by the dataset instance)
#define D_DIM   1024
#define E_DIM   64
#define TOPK    8
#define B_DIM   4
#define ALPHA   0.1f
#define EPS_R   1e-20f

#define TPB     128      // tokens per block
#define THREADS 256
#define KC      32       // k-chunk
#define XS_STR  36       // padded smem row stride (floats)
#define WS_STR  36
#define JT      4        // tokens per thread (j-tiles)

// scratch for aux-loss stats (no allocation allowed -> device globals)
__device__ float g_ce[B_DIM * E_DIM];
__device__ float g_ssum[B_DIM * E_DIM];

__global__ void zero_scratch_kernel() {
    int i = threadIdx.x;
    if (i < B_DIM * E_DIM) { g_ce[i] = 0.0f; g_ssum[i] = 0.0f; }
}

__global__ __launch_bounds__(THREADS, 1)
void moe_gate_kernel(const float* __restrict__ x,
                     const float* __restrict__ W,
                     float* __restrict__ out_idx,
                     float* __restrict__ out_w,
                     int S)
{
    __shared__ float xs[TPB * XS_STR];     // 18 KB
    __shared__ float ws[E_DIM * WS_STR];   // 9 KB
    __shared__ float sm_cnt[E_DIM];
    __shared__ float sm_ssum[E_DIM];

    const int tid = threadIdx.x;
    const int et  = tid & 7;      // expert-thread 0..7   (owns experts et + 8r)
    const int tt  = tid >> 3;     // token-thread  0..31  (owns tokens tt + 32j)
    const long t0 = (long)blockIdx.x * TPB;

    float acc[JT][8];   // Kahan running sums
    float cmp[JT][8];   // Kahan compensation
#pragma unroll
    for (int j = 0; j < JT; j++)
#pragma unroll
        for (int r = 0; r < 8; r++) { acc[j][r] = 0.0f; cmp[j][r] = 0.0f; }

    // ---------------- GEMM: logits[tok][e] = x . W[e] ----------------
    for (int k0 = 0; k0 < D_DIM; k0 += KC) {
        __syncthreads();
        // load x tile: 128 tokens x 32 floats = 1024 float4, 4 per thread
#pragma unroll
        for (int p = 0; p < 4; p++) {
            int idx = tid + THREADS * p;
            int tok = idx >> 3;
            int kq  = idx & 7;
            float4 v = *(const float4*)&x[(t0 + tok) * D_DIM + k0 + kq * 4];
            float* dst = &xs[tok * XS_STR + kq * 4];
            dst[0] = v.x; dst[1] = v.y; dst[2] = v.z; dst[3] = v.w;
        }
        // load W tile: 64 experts x 32 floats = 512 float4, 2 per thread
#pragma unroll
        for (int p = 0; p < 2; p++) {
            int idx = tid + THREADS * p;
            int e  = idx >> 3;
            int kq = idx & 7;
            float4 v = *(const float4*)&W[e * D_DIM + k0 + kq * 4];
            float* dst = &ws[e * WS_STR + kq * 4];
            dst[0] = v.x; dst[1] = v.y; dst[2] = v.z; dst[3] = v.w;
        }
        __syncthreads();

        // chunk-local accumulation (32 terms) in plain FMA
        float cacc[JT][8];
#pragma unroll
        for (int j = 0; j < JT; j++)
#pragma unroll
            for (int r = 0; r < 8; r++) cacc[j][r] = 0.0f;

#pragma unroll
        for (int kq = 0; kq < 8; kq++) {
            float4 xv[JT], wv[8];
#pragma unroll
            for (int j = 0; j < JT; j++)
                xv[j] = *(const float4*)&xs[(tt + 32 * j) * XS_STR + kq * 4];
#pragma unroll
            for (int r = 0; r < 8; r++)
                wv[r] = *(const float4*)&ws[(et + 8 * r) * WS_STR + kq * 4];
#pragma unroll
            for (int j = 0; j < JT; j++)
#pragma unroll
                for (int r = 0; r < 8; r++) {
                    cacc[j][r] += xv[j].x * wv[r].x;
                    cacc[j][r] += xv[j].y * wv[r].y;
                    cacc[j][r] += xv[j].z * wv[r].z;
                    cacc[j][r] += xv[j].w * wv[r].w;
                }
        }

        // Kahan-fold chunk sums into running accumulators
#pragma unroll
        for (int j = 0; j < JT; j++)
#pragma unroll
            for (int r = 0; r < 8; r++) {
                float y = cacc[j][r] - cmp[j][r];
                float t = acc[j][r] + y;
                cmp[j][r] = (t - acc[j][r]) - y;
                acc[j][r] = t;
            }
    }

    // ---------------- epilogue: softmax + top-8 + stats ----------------
    __syncthreads();
    if (tid < E_DIM) { sm_cnt[tid] = 0.0f; sm_ssum[tid] = 0.0f; }
    __syncthreads();

    const unsigned fullmask = 0xffffffffu;
    float loc_ssum[8];
#pragma unroll
    for (int r = 0; r < 8; r++) loc_ssum[r] = 0.0f;

#pragma unroll 1
    for (int j = 0; j < JT; j++) {
        // softmax over 64 experts split across 8 lanes (et group) x 8 regs
        float m = acc[j][0];
#pragma unroll
        for (int r = 1; r < 8; r++) m = fmaxf(m, acc[j][r]);
#pragma unroll
        for (int d = 1; d < 8; d <<= 1)
            m = fmaxf(m, __shfl_xor_sync(fullmask, m, d));

        float sc[8];
        float s = 0.0f;
#pragma unroll
        for (int r = 0; r < 8; r++) { sc[r] = expf(acc[j][r] - m); s += sc[r]; }
#pragma unroll
        for (int d = 1; d < 8; d <<= 1)
            s += __shfl_xor_sync(fullmask, s, d);
        // exact IEEE division to mirror XLA softmax
#pragma unroll
        for (int r = 0; r < 8; r++) { sc[r] = sc[r] / s; loc_ssum[r] += sc[r]; }

        // iterative top-8 (destructive on sc); tie-break: lower expert index
        float tv[TOPK]; int ti[TOPK];
#pragma unroll 1
        for (int it = 0; it < TOPK; it++) {
            float bv = -1.0f; int bi = E_DIM;
#pragma unroll
            for (int r = 0; r < 8; r++) {
                if (sc[r] > bv) { bv = sc[r]; bi = et + 8 * r; }
            }
#pragma unroll
            for (int d = 1; d < 8; d <<= 1) {
                float ov = __shfl_xor_sync(fullmask, bv, d);
                int   oi = __shfl_xor_sync(fullmask, bi, d);
                if (ov > bv || (ov == bv && oi < bi)) { bv = ov; bi = oi; }
            }
            if ((bi & 7) == et) sc[bi >> 3] = -1.0f;   // owner clears winner
            tv[it] = bv; ti[it] = bi;
        }

        if (et == 0) {
            float wsum = 0.0f;
#pragma unroll
            for (int it = 0; it < TOPK; it++) wsum += tv[it];
            wsum += EPS_R;
            long t = t0 + tt + 32 * j;
#pragma unroll
            for (int it = 0; it < TOPK; it++) {
                out_idx[t * TOPK + it] = (float)ti[it];
                out_w  [t * TOPK + it] = tv[it] / wsum;
                atomicAdd(&sm_cnt[ti[it]], 1.0f);
            }
        }
    }

#pragma unroll
    for (int r = 0; r < 8; r++)
        atomicAdd(&sm_ssum[et + 8 * r], loc_ssum[r]);
    __syncthreads();

    if (tid < E_DIM) {
        int b = (int)(t0 / (long)S);           // block is batch-aligned (128 | 8192)
        atomicAdd(&g_ce[b * E_DIM + tid],   sm_cnt[tid]);
        atomicAdd(&g_ssum[b * E_DIM + tid], sm_ssum[tid]);
    }
}

__global__ void aux_kernel(float* __restrict__ out_aux, int S) {
    __shared__ float red[256];
    int tid = threadIdx.x;
    float v = 0.0f;
    if (tid < B_DIM * E_DIM) v = g_ce[tid] * g_ssum[tid];
    red[tid] = v;
    __syncthreads();
    for (int off = 128; off > 0; off >>= 1) {
        if (tid < off) red[tid] += red[tid + off];
        __syncthreads();
    }
    if (tid == 0)
        out_aux[0] = red[0] / (float)S / (float)B_DIM * ALPHA;
}

extern "C" void kernel_launch(void* const* d_in, const int* in_sizes, int n_in,
                              void* d_out, int out_size) {
    const float* x = (const float*)d_in[0];
    const float* W = (const float*)d_in[1];
    const int T = in_sizes[0] / D_DIM;     // 32768
    const int S = T / B_DIM;               // 8192

    float* out     = (float*)d_out;
    float* out_idx = out;                         // [T,8] indices as float
    float* out_w   = out + (size_t)T * TOPK;      // [T,8] weights
    float* out_aux = out + (out_size - 1);        // scalar aux loss

    zero_scratch_kernel<<<1, 256>>>();
    moe_gate_kernel<<<T / TPB, THREADS>>>(x, W, out_idx, out_w, S);
    aux_kernel<<<1, 256>>>(out_aux, S);
}

// round 3
// speedup vs baseline: 1.1907x; 1.1907x over previous
#include <cuda_runtime.h>

// Problem constants (fixed by the dataset instance)
#define D_DIM   1024
#define E_DIM   64
#define TOPK    8
#define B_DIM   4
#define ALPHA   0.1f
#define EPS_R   1e-20f

#define TPB     64       // tokens per block
#define THREADS 128
#define KC      32       // k-chunk
#define XS_STR  36       // padded smem row stride (floats)
#define WS_STR  36
#define JT      4        // tokens per thread (j-tiles)

// scratch for aux-loss stats (no allocation allowed -> device globals)
__device__ float g_ce[B_DIM * E_DIM];
__device__ float g_ssum[B_DIM * E_DIM];

__global__ void zero_scratch_kernel() {
    int i = threadIdx.x;
    if (i < B_DIM * E_DIM) { g_ce[i] = 0.0f; g_ssum[i] = 0.0f; }
}

// packed f32x2 FMA: d.lo += a.lo*b.lo; d.hi += a.hi*b.hi  (one issue slot)
__device__ __forceinline__ void fma2(unsigned long long& d,
                                     unsigned long long a,
                                     unsigned long long b) {
    asm("fma.rn.f32x2 %0, %1, %2, %0;" : "+l"(d) : "l"(a), "l"(b));
}

__device__ __forceinline__ float fold2(unsigned long long v) {
    float lo, hi;
    asm("mov.b64 {%0, %1}, %2;" : "=f"(lo), "=f"(hi) : "l"(v));
    return lo + hi;
}

__global__ __launch_bounds__(THREADS, 2)
void moe_gate_kernel(const float* __restrict__ x,
                     const float* __restrict__ W,
                     float* __restrict__ out_idx,
                     float* __restrict__ out_w,
                     int S)
{
    __shared__ float xs[TPB * XS_STR];     // 9 KB
    __shared__ float ws[E_DIM * WS_STR];   // 9 KB
    __shared__ float sm_cnt[E_DIM];
    __shared__ float sm_ssum[E_DIM];

    const int tid = threadIdx.x;
    const int et  = tid & 7;      // expert-thread 0..7   (owns experts et + 8r)
    const int tt  = tid >> 3;     // token-thread  0..15  (owns tokens tt + 16j)
    const long t0 = (long)blockIdx.x * TPB;

    float acc[JT][8];   // Kahan running sums
    float cmp[JT][8];   // Kahan compensation
#pragma unroll
    for (int j = 0; j < JT; j++)
#pragma unroll
        for (int r = 0; r < 8; r++) { acc[j][r] = 0.0f; cmp[j][r] = 0.0f; }

    // ---------------- GEMM: logits[tok][e] = x . W[e] ----------------
    for (int k0 = 0; k0 < D_DIM; k0 += KC) {
        __syncthreads();
        // load x tile: 64 tokens x 32 floats = 512 float4, 4 per thread
#pragma unroll
        for (int p = 0; p < 4; p++) {
            int idx = tid + THREADS * p;
            int tok = idx >> 3;
            int kq  = idx & 7;
            float4 v = *(const float4*)&x[(t0 + tok) * D_DIM + k0 + kq * 4];
            float* dst = &xs[tok * XS_STR + kq * 4];
            dst[0] = v.x; dst[1] = v.y; dst[2] = v.z; dst[3] = v.w;
        }
        // load W tile: 64 experts x 32 floats = 512 float4, 4 per thread
#pragma unroll
        for (int p = 0; p < 4; p++) {
            int idx = tid + THREADS * p;
            int e  = idx >> 3;
            int kq = idx & 7;
            float4 v = *(const float4*)&W[e * D_DIM + k0 + kq * 4];
            float* dst = &ws[e * WS_STR + kq * 4];
            dst[0] = v.x; dst[1] = v.y; dst[2] = v.z; dst[3] = v.w;
        }
        __syncthreads();

        // chunk-local accumulation: even/odd k partials packed in f32x2
        unsigned long long cacc2[JT][8];
#pragma unroll
        for (int j = 0; j < JT; j++)
#pragma unroll
            for (int r = 0; r < 8; r++) cacc2[j][r] = 0ULL;

#pragma unroll
        for (int kq = 0; kq < 8; kq++) {
            ulonglong2 xv[JT], wv[8];
#pragma unroll
            for (int j = 0; j < JT; j++)
                xv[j] = *(const ulonglong2*)&xs[(tt + 16 * j) * XS_STR + kq * 4];
#pragma unroll
            for (int r = 0; r < 8; r++)
                wv[r] = *(const ulonglong2*)&ws[(et + 8 * r) * WS_STR + kq * 4];
#pragma unroll
            for (int j = 0; j < JT; j++)
#pragma unroll
                for (int r = 0; r < 8; r++) {
                    fma2(cacc2[j][r], xv[j].x, wv[r].x);
                    fma2(cacc2[j][r], xv[j].y, wv[r].y);
                }
        }

        // fold packed partials and Kahan-add into running accumulators
#pragma unroll
        for (int j = 0; j < JT; j++)
#pragma unroll
            for (int r = 0; r < 8; r++) {
                float c = fold2(cacc2[j][r]);
                float y = c - cmp[j][r];
                float t = acc[j][r] + y;
                cmp[j][r] = (t - acc[j][r]) - y;
                acc[j][r] = t;
            }
    }

    // ---------------- epilogue: softmax + top-8 + stats ----------------
    __syncthreads();
    if (tid < E_DIM) { sm_cnt[tid] = 0.0f; sm_ssum[tid] = 0.0f; }
    __syncthreads();

    const unsigned fullmask = 0xffffffffu;
    float loc_ssum[8];
#pragma unroll
    for (int r = 0; r < 8; r++) loc_ssum[r] = 0.0f;

#pragma unroll 1
    for (int j = 0; j < JT; j++) {
        // softmax over 64 experts split across 8 lanes (et group) x 8 regs
        float m = acc[j][0];
#pragma unroll
        for (int r = 1; r < 8; r++) m = fmaxf(m, acc[j][r]);
#pragma unroll
        for (int d = 1; d < 8; d <<= 1)
            m = fmaxf(m, __shfl_xor_sync(fullmask, m, d));

        float sc[8];
        float s = 0.0f;
#pragma unroll
        for (int r = 0; r < 8; r++) { sc[r] = expf(acc[j][r] - m); s += sc[r]; }
#pragma unroll
        for (int d = 1; d < 8; d <<= 1)
            s += __shfl_xor_sync(fullmask, s, d);
        // exact IEEE division to mirror XLA softmax
#pragma unroll
        for (int r = 0; r < 8; r++) { sc[r] = sc[r] / s; loc_ssum[r] += sc[r]; }

        // iterative top-8 (destructive on sc); tie-break: lower expert index
        float tv[TOPK]; int ti[TOPK];
#pragma unroll 1
        for (int it = 0; it < TOPK; it++) {
            float bv = -1.0f; int bi = E_DIM;
#pragma unroll
            for (int r = 0; r < 8; r++) {
                if (sc[r] > bv) { bv = sc[r]; bi = et + 8 * r; }
            }
#pragma unroll
            for (int d = 1; d < 8; d <<= 1) {
                float ov = __shfl_xor_sync(fullmask, bv, d);
                int   oi = __shfl_xor_sync(fullmask, bi, d);
                if (ov > bv || (ov == bv && oi < bi)) { bv = ov; bi = oi; }
            }
            if ((bi & 7) == et) sc[bi >> 3] = -1.0f;   // owner clears winner
            tv[it] = bv; ti[it] = bi;
        }

        if (et == 0) {
            float wsum = 0.0f;
#pragma unroll
            for (int it = 0; it < TOPK; it++) wsum += tv[it];
            wsum += EPS_R;
            long t = t0 + tt + 16 * j;
#pragma unroll
            for (int it = 0; it < TOPK; it++) {
                out_idx[t * TOPK + it] = (float)ti[it];
                out_w  [t * TOPK + it] = tv[it] / wsum;
                atomicAdd(&sm_cnt[ti[it]], 1.0f);
            }
        }
    }

#pragma unroll
    for (int r = 0; r < 8; r++)
        atomicAdd(&sm_ssum[et + 8 * r], loc_ssum[r]);
    __syncthreads();

    if (tid < E_DIM) {
        int b = (int)(t0 / (long)S);           // block is batch-aligned (64 | 8192)
        atomicAdd(&g_ce[b * E_DIM + tid],   sm_cnt[tid]);
        atomicAdd(&g_ssum[b * E_DIM + tid], sm_ssum[tid]);
    }
}

__global__ void aux_kernel(float* __restrict__ out_aux, int S) {
    __shared__ float red[256];
    int tid = threadIdx.x;
    float v = 0.0f;
    if (tid < B_DIM * E_DIM) v = g_ce[tid] * g_ssum[tid];
    red[tid] = v;
    __syncthreads();
    for (int off = 128; off > 0; off >>= 1) {
        if (tid < off) red[tid] += red[tid + off];
        __syncthreads();
    }
    if (tid == 0)
        out_aux[0] = red[0] / (float)S / (float)B_DIM * ALPHA;
}

extern "C" void kernel_launch(void* const* d_in, const int* in_sizes, int n_in,
                              void* d_out, int out_size) {
    const float* x = (const float*)d_in[0];
    const float* W = (const float*)d_in[1];
    const int T = in_sizes[0] / D_DIM;     // 32768
    const int S = T / B_DIM;               // 8192

    float* out     = (float*)d_out;
    float* out_idx = out;                         // [T,8] indices as float
    float* out_w   = out + (size_t)T * TOPK;      // [T,8] weights
    float* out_aux = out + (out_size - 1);        // scalar aux loss

    zero_scratch_kernel<<<1, 256>>>();
    moe_gate_kernel<<<T / TPB, THREADS>>>(x, W, out_idx, out_w, S);
    aux_kernel<<<1, 256>>>(out_aux, S);
}